// round 7
// baseline (speedup 1.0000x reference)
#include <cuda_runtime.h>
#include <cuda_bf16.h>
#include <cstdint>

// ---------------------------------------------------------------------------
// HybridGNN: 2-layer bipartite mean-SAGE + edge classifier.
// R5: all fp32->bf16 hi/lo splitting hoisted out of the GEMM (weights/x in
// setup, means in pull, h/z in GEMM epilogue). GEMM staging is a pure copy
// via cp.async with a 2-stage double-buffered pipeline. mma.sync bf16,
// 3 accumulation passes (hi*hi, hi*lo, lo*hi).
// ---------------------------------------------------------------------------

#define NN    50000
#define DIN   64
#define HH    128
#define EMAX  1000000
#define ETGT  500000

// ---- split-plane element offsets (bf16 planes g_sh / g_sl) ----
#define S_M1M 0
#define S_M1U 3200000
#define S_M2M 6400000
#define S_M2U 12800000
#define S_HM  19200000
#define S_HU  25600000
#define S_ZM  32000000
#define S_ZU  38400000
#define S_XU  44800000
#define S_XM  48000000
#define S_W   51200000
#define S_TOTAL 51331072

// weight sub-offsets within S_W
#define W1UL 0
#define W1UR 8192
#define W1ML 16384
#define W1MR 24576
#define W2UL 32768
#define W2UR 49152
#define W2ML 65536
#define W2MR 81920
#define WC   98304

// ---------------- scratch ----------------
__device__ int g_stride;
__device__ int g_deg[2][NN];
__device__ int g_cur[2][NN];
__device__ int g_off[2][NN + 1];
__device__ int g_csr[2][EMAX];

__device__ float g_h_m[NN * HH];
__device__ float g_h_u[NN * HH];
__device__ float g_Pu[NN * HH];
__device__ float g_Pm[NN * HH];

__device__ __nv_bfloat16 g_sh[S_TOTAL];
__device__ __nv_bfloat16 g_sl[S_TOTAL];

__device__ __forceinline__ float* gbuf(int id) {
    switch (id) {
        case 0: return g_h_m; case 1: return g_h_u;
        case 2: return g_Pu;  case 3: return g_Pm;
    }
    return nullptr;
}

__device__ __forceinline__ uint32_t pack_bf16(float a, float b) {
    __nv_bfloat162 h = __floats2bfloat162_rn(a, b);
    return *(uint32_t*)&h;
}

// split two floats -> hi pack + lo pack
__device__ __forceinline__ void split2(float x, float y, uint32_t& hi, uint32_t& lo) {
    float hx = __bfloat162float(__float2bfloat16_rn(x));
    float hy = __bfloat162float(__float2bfloat16_rn(y));
    hi = pack_bf16(x, y);
    lo = pack_bf16(x - hx, y - hy);
}

// ---------------- setup: zero counters + detect + split weights & x ----------
struct SetupArgs {
    const float* src[11];
    int dstoff[11];
    int start[12];      // pair prefix sums
    const int* e_detect;
};

__global__ void setup_kernel(SetupArgs a) {
    int idx = blockIdx.x * blockDim.x + threadIdx.x;
    if (idx < NN) {
        g_deg[0][idx] = 0; g_deg[1][idx] = 0;
        g_cur[0][idx] = 0; g_cur[1][idx] = 0;
    }
    if (blockIdx.x == 0 && threadIdx.x < 32) {
        int lane = threadIdx.x, v = 0;
#pragma unroll
        for (int i = 0; i < 4; ++i) v |= a.e_detect[2 * (lane + 32 * i) + 1];
        unsigned nz = __ballot_sync(0xffffffffu, v != 0);
        if (lane == 0) g_stride = (nz == 0u) ? 2 : 1;
    }
    if (idx >= a.start[11]) return;
    int s = 0;
    while (idx >= a.start[s + 1]) ++s;
    int rel = idx - a.start[s];
    float2 v = ((const float2*)a.src[s])[rel];
    uint32_t hi, lo;
    split2(v.x, v.y, hi, lo);
    int off = a.dstoff[s] + 2 * rel;
    *(uint32_t*)&g_sh[off] = hi;
    *(uint32_t*)&g_sl[off] = lo;
}

// ---------------- CSR build ----------------
__global__ void count_both_kernel(const int* __restrict__ e0,
                                  const int* __restrict__ e1, int E) {
    int i = blockIdx.x * blockDim.x + threadIdx.x;
    if (i >= E) return;
    int W = blockIdx.y;
    const int* e = W ? e1 : e0;
    int st = g_stride;
    atomicAdd(&g_deg[W][e[st * (E + i)]], 1);
}

__global__ void scan_both_kernel() {
    __shared__ int s[1024];
    int W = blockIdx.x;
    int t = threadIdx.x;
    const int n = NN;
    int per = (n + 1023) / 1024;
    int start = t * per;
    int end = start + per; if (end > n) end = n; if (start > n) start = n;
    int sum = 0;
    for (int i = start; i < end; ++i) sum += g_deg[W][i];
    s[t] = sum;
    __syncthreads();
    for (int d = 1; d < 1024; d <<= 1) {
        int v = (t >= d) ? s[t - d] : 0;
        __syncthreads();
        s[t] += v;
        __syncthreads();
    }
    int run = (t == 0) ? 0 : s[t - 1];
    for (int i = start; i < end; ++i) { g_off[W][i] = run; run += g_deg[W][i]; }
    if (t == 1023) g_off[W][n] = s[1023];
}

__global__ void scatter_both_kernel(const int* __restrict__ e0,
                                    const int* __restrict__ e1, int E) {
    int i = blockIdx.x * blockDim.x + threadIdx.x;
    if (i >= E) return;
    int W = blockIdx.y;
    const int* e = W ? e1 : e0;
    int st = g_stride;
    int row = e[st * i];
    int col = e[st * (E + i)];
    int p = g_off[W][col] + atomicAdd(&g_cur[W][col], 1);
    g_csr[W][p] = row;
}

// ---------------- pull-based mean aggregation -> split planes ----------------
template <int D>
__global__ void pull_pair_kernel(const float* __restrict__ x0, int x0_id,
                                 const float* __restrict__ x1, int x1_id,
                                 int oS0, int oS1) {
    int W = blockIdx.y;
    int w    = (blockIdx.x * blockDim.x + threadIdx.x) >> 5;
    int lane = threadIdx.x & 31;
    if (w >= NN) return;
    const float* xsrc = W ? (x1 ? x1 : gbuf(x1_id)) : (x0 ? x0 : gbuf(x0_id));
    int oS = W ? oS1 : oS0;
    const int* __restrict__ csr = g_csr[W];
    int s0 = g_off[W][w], s1 = g_off[W][w + 1];
    float inv = 1.0f / fmaxf((float)(s1 - s0), 1.0f);
    if (D == 128) {
        const float4* xv = (const float4*)xsrc;
        float4 a0 = make_float4(0.f, 0.f, 0.f, 0.f), a1 = a0;
        int j = s0;
        for (; j + 1 < s1; j += 2) {
            int sa = csr[j], sb = csr[j + 1];
            float4 va = __ldg(&xv[sa * 32 + lane]);
            float4 vb = __ldg(&xv[sb * 32 + lane]);
            a0.x += va.x; a0.y += va.y; a0.z += va.z; a0.w += va.w;
            a1.x += vb.x; a1.y += vb.y; a1.z += vb.z; a1.w += vb.w;
        }
        if (j < s1) {
            float4 va = __ldg(&xv[csr[j] * 32 + lane]);
            a0.x += va.x; a0.y += va.y; a0.z += va.z; a0.w += va.w;
        }
        float4 m = make_float4((a0.x + a1.x) * inv, (a0.y + a1.y) * inv,
                               (a0.z + a1.z) * inv, (a0.w + a1.w) * inv);
        uint32_t h0, l0, h1, l1;
        split2(m.x, m.y, h0, l0);
        split2(m.z, m.w, h1, l1);
        int off = oS + w * 128 + lane * 4;
        *(uint2*)&g_sh[off] = make_uint2(h0, h1);
        *(uint2*)&g_sl[off] = make_uint2(l0, l1);
    } else {
        const float2* xv = (const float2*)xsrc;
        float2 a0 = make_float2(0.f, 0.f), a1 = a0;
        int j = s0;
        for (; j + 1 < s1; j += 2) {
            int sa = csr[j], sb = csr[j + 1];
            float2 va = __ldg(&xv[sa * 32 + lane]);
            float2 vb = __ldg(&xv[sb * 32 + lane]);
            a0.x += va.x; a0.y += va.y;
            a1.x += vb.x; a1.y += vb.y;
        }
        if (j < s1) {
            float2 va = __ldg(&xv[csr[j] * 32 + lane]);
            a0.x += va.x; a0.y += va.y;
        }
        float mx = (a0.x + a1.x) * inv, my = (a0.y + a1.y) * inv;
        uint32_t hi, lo;
        split2(mx, my, hi, lo);
        int off = oS + w * 64 + lane * 2;
        *(uint32_t*)&g_sh[off] = hi;
        *(uint32_t*)&g_sl[off] = lo;
    }
}

// ---------------- pre-split mma.sync paired GEMM (cp.async pipeline) --------
#define SROW 40
#define P_PLANE 5120             // 128 * SROW elements per plane
#define PB (P_PLANE * 2)         // plane stride in bytes
#define STAGEB (4 * PB)          // stage stride in bytes
#define SMEM_DYN (2 * STAGEB)    // 81920 bytes

struct Chunk { int a_base, b_base, lda, ldb; };
struct GArgs {
    Chunk ch[2][8];
    const float* bias[2];
    int outF[2];     // fp32 gbuf id or -1
    int outS[2];     // split plane base or -1
    int nchunks, doRelu;
};

__device__ __forceinline__ uint32_t smem_u32(const void* p) {
    uint32_t a;
    asm("{ .reg .u64 t; cvta.to.shared.u64 t, %1; cvt.u32.u64 %0, t; }"
        : "=r"(a) : "l"(p));
    return a;
}

#define CP16(d, s) asm volatile("cp.async.cg.shared.global [%0], [%1], 16;" \
                                :: "r"(d), "l"(s) : "memory")
#define CPCOMMIT() asm volatile("cp.async.commit_group;" ::: "memory")
#define CPWAIT1()  asm volatile("cp.async.wait_group 1;" ::: "memory")
#define CPWAIT0()  asm volatile("cp.async.wait_group 0;" ::: "memory")

__device__ __forceinline__ void ldsm4(uint32_t* r, uint32_t addr) {
    asm volatile("ldmatrix.sync.aligned.m8n8.x4.shared.b16 {%0,%1,%2,%3}, [%4];"
        : "=r"(r[0]), "=r"(r[1]), "=r"(r[2]), "=r"(r[3]) : "r"(addr));
}

__device__ __forceinline__ void mma16816(float* c, const uint32_t* a, const uint32_t* b) {
    asm volatile(
        "mma.sync.aligned.m16n8k16.row.col.f32.bf16.bf16.f32 "
        "{%0,%1,%2,%3}, {%4,%5,%6,%7}, {%8,%9}, {%0,%1,%2,%3};"
        : "+f"(c[0]), "+f"(c[1]), "+f"(c[2]), "+f"(c[3])
        : "r"(a[0]), "r"(a[1]), "r"(a[2]), "r"(a[3]), "r"(b[0]), "r"(b[1]));
}

__global__ __launch_bounds__(256, 2)
void gemm_mma_kernel(GArgs ga) {
    extern __shared__ __nv_bfloat16 sm[];
    const uint32_t smb = smem_u32(sm);

    const int g   = blockIdx.y;
    const int t   = threadIdx.x;
    const int wid = t >> 5, lane = t & 31;
    const int warp_m = wid & 3;
    const int warp_n = wid >> 2;
    const int r0 = blockIdx.x * 128;

    float acc[2][8][4];
#pragma unroll
    for (int i = 0; i < 2; ++i)
#pragma unroll
        for (int j = 0; j < 8; ++j) {
            acc[i][j][0] = 0.f; acc[i][j][1] = 0.f;
            acc[i][j][2] = 0.f; acc[i][j][3] = 0.f;
        }

    const int srow = t >> 1;
    const int shalf = (t & 1) * 16;
    int rowA = r0 + srow;
    if (rowA >= NN) rowA = NN - 1;   // clamped rows discarded in epilogue

    const int lg = lane >> 3, lr = lane & 7;
    const int roff = (lg & 1) * 8 + lr;
    const int koff = (lg >> 1) * 8;
    const int n = ga.nchunks;

    // stage issue: pure cp.async copies from pre-split planes
    auto issue = [&](int c, int st) {
        const Chunk ch = ga.ch[g][c];
        const __nv_bfloat16* ah = &g_sh[ch.a_base + rowA * ch.lda + shalf];
        const __nv_bfloat16* al = &g_sl[ch.a_base + rowA * ch.lda + shalf];
        const __nv_bfloat16* bh = &g_sh[ch.b_base + srow * ch.ldb + shalf];
        const __nv_bfloat16* bl = &g_sl[ch.b_base + srow * ch.ldb + shalf];
        uint32_t d = smb + st * STAGEB + (srow * SROW + shalf) * 2;
        CP16(d,           ah); CP16(d + 16,           ah + 8);
        CP16(d + PB,      al); CP16(d + PB + 16,      al + 8);
        CP16(d + 2 * PB,  bh); CP16(d + 2 * PB + 16,  bh + 8);
        CP16(d + 3 * PB,  bl); CP16(d + 3 * PB + 16,  bl + 8);
    };

    auto compute = [&](int st) {
        uint32_t b0 = smb + st * STAGEB;
#pragma unroll
        for (int k0 = 0; k0 < 32; k0 += 16) {
            uint32_t aH[2][4], aL[2][4], bH[4][4], bL[4][4];
#pragma unroll
            for (int mi = 0; mi < 2; ++mi) {
                int m = warp_m * 32 + mi * 16 + roff;
                uint32_t off = b0 + (uint32_t)(m * SROW + k0 + koff) * 2;
                ldsm4(aH[mi], off);
                ldsm4(aL[mi], off + PB);
            }
#pragma unroll
            for (int ni = 0; ni < 4; ++ni) {
                int nrow = warp_n * 64 + ni * 16 + roff;
                uint32_t off = b0 + (uint32_t)(nrow * SROW + k0 + koff) * 2;
                ldsm4(bH[ni], off + 2 * PB);
                ldsm4(bL[ni], off + 3 * PB);
            }
#pragma unroll
            for (int mi = 0; mi < 2; ++mi)
#pragma unroll
                for (int ni = 0; ni < 4; ++ni)
#pragma unroll
                    for (int sub = 0; sub < 2; ++sub) {
                        uint32_t b0h[2] = {bH[ni][sub], bH[ni][2 + sub]};
                        uint32_t b0l[2] = {bL[ni][sub], bL[ni][2 + sub]};
                        float* cc = acc[mi][ni * 2 + sub];
                        mma16816(cc, aH[mi], b0h);
                        mma16816(cc, aH[mi], b0l);
                        mma16816(cc, aL[mi], b0h);
                    }
        }
    };

    issue(0, 0); CPCOMMIT();
    for (int c = 0; c < n; ++c) {
        if (c + 1 < n) { issue(c + 1, (c + 1) & 1); CPCOMMIT(); CPWAIT1(); }
        else           { CPWAIT0(); }
        __syncthreads();
        compute(c & 1);
        __syncthreads();
    }

    // ---- epilogue ----
    const float* bias = ga.bias[g];
    float* outF = (ga.outF[g] >= 0) ? gbuf(ga.outF[g]) : nullptr;
    const int oS = ga.outS[g];
    const int tg = lane >> 2, tid4 = lane & 3;
#pragma unroll
    for (int j = 0; j < 8; ++j) {
        int col = warp_n * 64 + j * 8 + tid4 * 2;
        float2 bb = bias ? *(const float2*)&bias[col] : make_float2(0.f, 0.f);
#pragma unroll
        for (int mi = 0; mi < 2; ++mi) {
            int row0 = r0 + warp_m * 32 + mi * 16 + tg;
            float* cc = acc[mi][j];
            float2 v0 = make_float2(cc[0] + bb.x, cc[1] + bb.y);
            float2 v1 = make_float2(cc[2] + bb.x, cc[3] + bb.y);
            if (ga.doRelu) {
                v0.x = fmaxf(v0.x, 0.f); v0.y = fmaxf(v0.y, 0.f);
                v1.x = fmaxf(v1.x, 0.f); v1.y = fmaxf(v1.y, 0.f);
            }
            if (row0 < NN) {
                if (outF) *(float2*)&outF[(size_t)row0 * 128 + col] = v0;
                if (oS >= 0) {
                    uint32_t hi, lo;
                    split2(v0.x, v0.y, hi, lo);
                    int off = oS + row0 * 128 + col;
                    *(uint32_t*)&g_sh[off] = hi;
                    *(uint32_t*)&g_sl[off] = lo;
                }
            }
            int row1 = row0 + 8;
            if (row1 < NN) {
                if (outF) *(float2*)&outF[(size_t)row1 * 128 + col] = v1;
                if (oS >= 0) {
                    uint32_t hi, lo;
                    split2(v1.x, v1.y, hi, lo);
                    int off = oS + row1 * 128 + col;
                    *(uint32_t*)&g_sh[off] = hi;
                    *(uint32_t*)&g_sl[off] = lo;
                }
            }
        }
    }
}

// ---------------- edge classifier ----------------
__global__ void edge_cls_kernel(const int* __restrict__ tei, int Et,
                                const float* __restrict__ Wc2,
                                const float* __restrict__ bc2,
                                float* __restrict__ out) {
    int w    = (blockIdx.x * blockDim.x + threadIdx.x) >> 5;
    int lane = threadIdx.x & 31;
    if (w >= Et) return;
    int st = g_stride;
    int ru = tei[st * w];
    int rm = tei[st * (Et + w)];
    float4 u  = __ldg(&((const float4*)g_Pu)[ru * 32 + lane]);
    float4 m  = __ldg(&((const float4*)g_Pm)[rm * 32 + lane]);
    float4 wv = __ldg(&((const float4*)Wc2)[lane]);
    float a = fmaxf(u.x + m.x, 0.f) * wv.x
            + fmaxf(u.y + m.y, 0.f) * wv.y
            + fmaxf(u.z + m.z, 0.f) * wv.z
            + fmaxf(u.w + m.w, 0.f) * wv.w;
#pragma unroll
    for (int o = 16; o; o >>= 1) a += __shfl_xor_sync(0xffffffffu, a, o);
    if (lane == 0) out[w] = a + bc2[0];
}

// ---------------- host launcher ----------------
extern "C" void kernel_launch(void* const* d_in, const int* in_sizes, int n_in,
                              void* d_out, int out_size) {
    const float* x_user  = (const float*)d_in[0];
    const float* x_merch = (const float*)d_in[1];
    const int*   e_um    = (const int*)d_in[2];
    const int*   e_mu    = (const int*)d_in[3];
    const int*   tei     = (const int*)d_in[4];
    const float* W1_um_l = (const float*)d_in[5];
    const float* b1_um_l = (const float*)d_in[6];
    const float* W1_um_r = (const float*)d_in[7];
    const float* W1_mu_l = (const float*)d_in[8];
    const float* b1_mu_l = (const float*)d_in[9];
    const float* W1_mu_r = (const float*)d_in[10];
    const float* W2_um_l = (const float*)d_in[11];
    const float* b2_um_l = (const float*)d_in[12];
    const float* W2_um_r = (const float*)d_in[13];
    const float* W2_mu_l = (const float*)d_in[14];
    const float* b2_mu_l = (const float*)d_in[15];
    const float* W2_mu_r = (const float*)d_in[16];
    const float* Wc1     = (const float*)d_in[17];
    const float* bc1     = (const float*)d_in[18];
    const float* Wc2     = (const float*)d_in[19];
    const float* bc2     = (const float*)d_in[20];

    const int E  = EMAX;
    const int Et = ETGT;
    float* out = (float*)d_out;

    cudaFuncSetAttribute(gemm_mma_kernel,
                         cudaFuncAttributeMaxDynamicSharedMemorySize, SMEM_DYN);

    // 1) setup: zero counters, dtype detect, split weights & x
    SetupArgs sa;
    const float* srcs[11] = {W1_um_l, W1_um_r, W1_mu_l, W1_mu_r,
                             W2_um_l, W2_um_r, W2_mu_l, W2_mu_r, Wc1,
                             x_user, x_merch};
    int doffs[11] = {S_W + W1UL, S_W + W1UR, S_W + W1ML, S_W + W1MR,
                     S_W + W2UL, S_W + W2UR, S_W + W2ML, S_W + W2MR, S_W + WC,
                     S_XU, S_XM};
    int pairs[11] = {4096, 4096, 4096, 4096, 8192, 8192, 8192, 8192, 16384,
                     1600000, 1600000};
    int run = 0;
    for (int i = 0; i < 11; ++i) {
        sa.src[i] = srcs[i]; sa.dstoff[i] = doffs[i];
        sa.start[i] = run; run += pairs[i];
    }
    sa.start[11] = run;
    sa.e_detect = e_um;
    setup_kernel<<<(run + 255) / 256, 256>>>(sa);

    // 2) CSR build
    const int EB = (E + 255) / 256;
    count_both_kernel<<<dim3(EB, 2), 256>>>(e_um, e_mu, E);
    scan_both_kernel<<<2, 1024>>>();
    scatter_both_kernel<<<dim3(EB, 2), 256>>>(e_um, e_mu, E);

    const int PB2 = (NN * 32 + 255) / 256;
    const int GB = (NN + 127) / 128;

    auto CHK = [](int ab, int bb, int lda, int ldb) {
        Chunk c; c.a_base = ab; c.b_base = bb; c.lda = lda; c.ldb = ldb; return c;
    };

    // 3) layer 1 (relu): h = relu([mean1 | x_self] @ W + b)
    pull_pair_kernel<64><<<dim3(PB2, 2), 256>>>(x_user, -1, x_merch, -1,
                                                S_M1M, S_M1U);
    GArgs g1;
    for (int q = 0; q < 2; ++q) {
        g1.ch[0][q]     = CHK(S_M1M + 32 * q, S_W + W1UL + 32 * q, 64, 64);
        g1.ch[0][2 + q] = CHK(S_XM  + 32 * q, S_W + W1UR + 32 * q, 64, 64);
        g1.ch[1][q]     = CHK(S_M1U + 32 * q, S_W + W1ML + 32 * q, 64, 64);
        g1.ch[1][2 + q] = CHK(S_XU  + 32 * q, S_W + W1MR + 32 * q, 64, 64);
    }
    g1.bias[0] = b1_um_l; g1.bias[1] = b1_mu_l;
    g1.outF[0] = 0; g1.outF[1] = 1;          // h fp32 (for pull2)
    g1.outS[0] = S_HM; g1.outS[1] = S_HU;    // h split (for gemm2)
    g1.nchunks = 4; g1.doRelu = 1;
    gemm_mma_kernel<<<dim3(GB, 2), 256, SMEM_DYN>>>(g1);

    // 4) layer 2 (no relu): z = [mean2 | h_self] @ W + b  (split only)
    pull_pair_kernel<128><<<dim3(PB2, 2), 256>>>(nullptr, 1, nullptr, 0,
                                                 S_M2M, S_M2U);
    GArgs g2;
    for (int q = 0; q < 4; ++q) {
        g2.ch[0][q]     = CHK(S_M2M + 32 * q, S_W + W2UL + 32 * q, 128, 128);
        g2.ch[0][4 + q] = CHK(S_HM  + 32 * q, S_W + W2UR + 32 * q, 128, 128);
        g2.ch[1][q]     = CHK(S_M2U + 32 * q, S_W + W2ML + 32 * q, 128, 128);
        g2.ch[1][4 + q] = CHK(S_HU  + 32 * q, S_W + W2MR + 32 * q, 128, 128);
    }
    g2.bias[0] = b2_um_l; g2.bias[1] = b2_mu_l;
    g2.outF[0] = -1; g2.outF[1] = -1;
    g2.outS[0] = S_ZM; g2.outS[1] = S_ZU;
    g2.nchunks = 8; g2.doRelu = 0;
    gemm_mma_kernel<<<dim3(GB, 2), 256, SMEM_DYN>>>(g2);

    // 5) classifier projections: Pu = z_u@Wc1a + bc1, Pm = z_m@Wc1b
    GArgs gc;
    for (int q = 0; q < 4; ++q) {
        gc.ch[0][q] = CHK(S_ZU + 32 * q, S_W + WC + 32 * q,       128, 256);
        gc.ch[1][q] = CHK(S_ZM + 32 * q, S_W + WC + 128 + 32 * q, 128, 256);
    }
    gc.bias[0] = bc1; gc.bias[1] = nullptr;
    gc.outF[0] = 2; gc.outF[1] = 3;
    gc.outS[0] = -1; gc.outS[1] = -1;
    gc.nchunks = 4; gc.doRelu = 0;
    gemm_mma_kernel<<<dim3(GB, 2), 256, SMEM_DYN>>>(gc);

    // 6) per-edge output
    edge_cls_kernel<<<(Et * 32 + 255) / 256, 256>>>(tei, Et, Wc2, bc2, out);
}

// round 8
// speedup vs baseline: 1.0031x; 1.0031x over previous
#include <cuda_runtime.h>
#include <cuda_bf16.h>
#include <cstdint>

// ---------------------------------------------------------------------------
// HybridGNN: 2-layer bipartite mean-SAGE + edge classifier.
// R5: all fp32->bf16 hi/lo splitting hoisted out of the GEMM (weights/x in
// setup, means in pull, h/z in GEMM epilogue). GEMM staging is a pure copy
// via cp.async with a 2-stage double-buffered pipeline. mma.sync bf16,
// 3 accumulation passes (hi*hi, hi*lo, lo*hi).
// ---------------------------------------------------------------------------

#define NN    50000
#define DIN   64
#define HH    128
#define EMAX  1000000
#define ETGT  500000

// ---- split-plane element offsets (bf16 planes g_sh / g_sl) ----
#define S_M1M 0
#define S_M1U 3200000
#define S_M2M 6400000
#define S_M2U 12800000
#define S_HM  19200000
#define S_HU  25600000
#define S_ZM  32000000
#define S_ZU  38400000
#define S_XU  44800000
#define S_XM  48000000
#define S_W   51200000
#define S_TOTAL 51331072

// weight sub-offsets within S_W
#define W1UL 0
#define W1UR 8192
#define W1ML 16384
#define W1MR 24576
#define W2UL 32768
#define W2UR 49152
#define W2ML 65536
#define W2MR 81920
#define WC   98304

// ---------------- scratch ----------------
__device__ int g_stride;
__device__ int g_deg[2][NN];
__device__ int g_cur[2][NN];
__device__ int g_off[2][NN + 1];
__device__ int g_csr[2][EMAX];

__device__ float g_h_m[NN * HH];
__device__ float g_h_u[NN * HH];
__device__ float g_Pu[NN * HH];
__device__ float g_Pm[NN * HH];

__device__ __nv_bfloat16 g_sh[S_TOTAL];
__device__ __nv_bfloat16 g_sl[S_TOTAL];

__device__ __forceinline__ float* gbuf(int id) {
    switch (id) {
        case 0: return g_h_m; case 1: return g_h_u;
        case 2: return g_Pu;  case 3: return g_Pm;
    }
    return nullptr;
}

__device__ __forceinline__ uint32_t pack_bf16(float a, float b) {
    __nv_bfloat162 h = __floats2bfloat162_rn(a, b);
    return *(uint32_t*)&h;
}

// split two floats -> hi pack + lo pack
__device__ __forceinline__ void split2(float x, float y, uint32_t& hi, uint32_t& lo) {
    float hx = __bfloat162float(__float2bfloat16_rn(x));
    float hy = __bfloat162float(__float2bfloat16_rn(y));
    hi = pack_bf16(x, y);
    lo = pack_bf16(x - hx, y - hy);
}

// ---------------- setup: zero counters + detect + split weights & x ----------
struct SetupArgs {
    const float* src[11];
    int dstoff[11];
    int start[12];      // pair prefix sums
    const int* e_detect;
};

__global__ void setup_kernel(SetupArgs a) {
    int idx = blockIdx.x * blockDim.x + threadIdx.x;
    if (idx < NN) {
        g_deg[0][idx] = 0; g_deg[1][idx] = 0;
        g_cur[0][idx] = 0; g_cur[1][idx] = 0;
    }
    if (blockIdx.x == 0 && threadIdx.x < 32) {
        int lane = threadIdx.x, v = 0;
#pragma unroll
        for (int i = 0; i < 4; ++i) v |= a.e_detect[2 * (lane + 32 * i) + 1];
        unsigned nz = __ballot_sync(0xffffffffu, v != 0);
        if (lane == 0) g_stride = (nz == 0u) ? 2 : 1;
    }
    if (idx >= a.start[11]) return;
    int s = 0;
    while (idx >= a.start[s + 1]) ++s;
    int rel = idx - a.start[s];
    float2 v = ((const float2*)a.src[s])[rel];
    uint32_t hi, lo;
    split2(v.x, v.y, hi, lo);
    int off = a.dstoff[s] + 2 * rel;
    *(uint32_t*)&g_sh[off] = hi;
    *(uint32_t*)&g_sl[off] = lo;
}

// ---------------- CSR build ----------------
__global__ void count_both_kernel(const int* __restrict__ e0,
                                  const int* __restrict__ e1, int E) {
    int i = blockIdx.x * blockDim.x + threadIdx.x;
    if (i >= E) return;
    int W = blockIdx.y;
    const int* e = W ? e1 : e0;
    int st = g_stride;
    atomicAdd(&g_deg[W][e[st * (E + i)]], 1);
}

__global__ void scan_both_kernel() {
    __shared__ int s[1024];
    int W = blockIdx.x;
    int t = threadIdx.x;
    const int n = NN;
    int per = (n + 1023) / 1024;
    int start = t * per;
    int end = start + per; if (end > n) end = n; if (start > n) start = n;
    int sum = 0;
    for (int i = start; i < end; ++i) sum += g_deg[W][i];
    s[t] = sum;
    __syncthreads();
    for (int d = 1; d < 1024; d <<= 1) {
        int v = (t >= d) ? s[t - d] : 0;
        __syncthreads();
        s[t] += v;
        __syncthreads();
    }
    int run = (t == 0) ? 0 : s[t - 1];
    for (int i = start; i < end; ++i) { g_off[W][i] = run; run += g_deg[W][i]; }
    if (t == 1023) g_off[W][n] = s[1023];
}

__global__ void scatter_both_kernel(const int* __restrict__ e0,
                                    const int* __restrict__ e1, int E) {
    int i = blockIdx.x * blockDim.x + threadIdx.x;
    if (i >= E) return;
    int W = blockIdx.y;
    const int* e = W ? e1 : e0;
    int st = g_stride;
    int row = e[st * i];
    int col = e[st * (E + i)];
    int p = g_off[W][col] + atomicAdd(&g_cur[W][col], 1);
    g_csr[W][p] = row;
}

// ---------------- pull-based mean aggregation -> split planes ----------------
template <int D>
__global__ void pull_pair_kernel(const float* __restrict__ x0, int x0_id,
                                 const float* __restrict__ x1, int x1_id,
                                 int oS0, int oS1) {
    int W = blockIdx.y;
    int w    = (blockIdx.x * blockDim.x + threadIdx.x) >> 5;
    int lane = threadIdx.x & 31;
    if (w >= NN) return;
    const float* xsrc = W ? (x1 ? x1 : gbuf(x1_id)) : (x0 ? x0 : gbuf(x0_id));
    int oS = W ? oS1 : oS0;
    const int* __restrict__ csr = g_csr[W];
    int s0 = g_off[W][w], s1 = g_off[W][w + 1];
    float inv = 1.0f / fmaxf((float)(s1 - s0), 1.0f);
    if (D == 128) {
        const float4* xv = (const float4*)xsrc;
        float4 a0 = make_float4(0.f, 0.f, 0.f, 0.f), a1 = a0;
        int j = s0;
        for (; j + 1 < s1; j += 2) {
            int sa = csr[j], sb = csr[j + 1];
            float4 va = __ldg(&xv[sa * 32 + lane]);
            float4 vb = __ldg(&xv[sb * 32 + lane]);
            a0.x += va.x; a0.y += va.y; a0.z += va.z; a0.w += va.w;
            a1.x += vb.x; a1.y += vb.y; a1.z += vb.z; a1.w += vb.w;
        }
        if (j < s1) {
            float4 va = __ldg(&xv[csr[j] * 32 + lane]);
            a0.x += va.x; a0.y += va.y; a0.z += va.z; a0.w += va.w;
        }
        float4 m = make_float4((a0.x + a1.x) * inv, (a0.y + a1.y) * inv,
                               (a0.z + a1.z) * inv, (a0.w + a1.w) * inv);
        uint32_t h0, l0, h1, l1;
        split2(m.x, m.y, h0, l0);
        split2(m.z, m.w, h1, l1);
        int off = oS + w * 128 + lane * 4;
        *(uint2*)&g_sh[off] = make_uint2(h0, h1);
        *(uint2*)&g_sl[off] = make_uint2(l0, l1);
    } else {
        const float2* xv = (const float2*)xsrc;
        float2 a0 = make_float2(0.f, 0.f), a1 = a0;
        int j = s0;
        for (; j + 1 < s1; j += 2) {
            int sa = csr[j], sb = csr[j + 1];
            float2 va = __ldg(&xv[sa * 32 + lane]);
            float2 vb = __ldg(&xv[sb * 32 + lane]);
            a0.x += va.x; a0.y += va.y;
            a1.x += vb.x; a1.y += vb.y;
        }
        if (j < s1) {
            float2 va = __ldg(&xv[csr[j] * 32 + lane]);
            a0.x += va.x; a0.y += va.y;
        }
        float mx = (a0.x + a1.x) * inv, my = (a0.y + a1.y) * inv;
        uint32_t hi, lo;
        split2(mx, my, hi, lo);
        int off = oS + w * 64 + lane * 2;
        *(uint32_t*)&g_sh[off] = hi;
        *(uint32_t*)&g_sl[off] = lo;
    }
}

// ---------------- pre-split mma.sync paired GEMM (cp.async pipeline) --------
#define SROW 40
#define P_PLANE 5120             // 128 * SROW elements per plane
#define PB (P_PLANE * 2)         // plane stride in bytes
#define STAGEB (4 * PB)          // stage stride in bytes
#define SMEM_DYN (2 * STAGEB)    // 81920 bytes

struct Chunk { int a_base, b_base, lda, ldb; };
struct GArgs {
    Chunk ch[2][8];
    const float* bias[2];
    int outF[2];     // fp32 gbuf id or -1
    int outS[2];     // split plane base or -1
    int nchunks, doRelu;
};

__device__ __forceinline__ uint32_t smem_u32(const void* p) {
    uint32_t a;
    asm("{ .reg .u64 t; cvta.to.shared.u64 t, %1; cvt.u32.u64 %0, t; }"
        : "=r"(a) : "l"(p));
    return a;
}

#define CP16(d, s) asm volatile("cp.async.cg.shared.global [%0], [%1], 16;" \
                                :: "r"(d), "l"(s) : "memory")
#define CPCOMMIT() asm volatile("cp.async.commit_group;" ::: "memory")
#define CPWAIT1()  asm volatile("cp.async.wait_group 1;" ::: "memory")
#define CPWAIT0()  asm volatile("cp.async.wait_group 0;" ::: "memory")

__device__ __forceinline__ void ldsm4(uint32_t* r, uint32_t addr) {
    asm volatile("ldmatrix.sync.aligned.m8n8.x4.shared.b16 {%0,%1,%2,%3}, [%4];"
        : "=r"(r[0]), "=r"(r[1]), "=r"(r[2]), "=r"(r[3]) : "r"(addr));
}

__device__ __forceinline__ void mma16816(float* c, const uint32_t* a, const uint32_t* b) {
    asm volatile(
        "mma.sync.aligned.m16n8k16.row.col.f32.bf16.bf16.f32 "
        "{%0,%1,%2,%3}, {%4,%5,%6,%7}, {%8,%9}, {%0,%1,%2,%3};"
        : "+f"(c[0]), "+f"(c[1]), "+f"(c[2]), "+f"(c[3])
        : "r"(a[0]), "r"(a[1]), "r"(a[2]), "r"(a[3]), "r"(b[0]), "r"(b[1]));
}

__global__ __launch_bounds__(256, 2)
void gemm_mma_kernel(GArgs ga) {
    extern __shared__ __nv_bfloat16 sm[];
    const uint32_t smb = smem_u32(sm);

    const int g   = blockIdx.y;
    const int t   = threadIdx.x;
    const int wid = t >> 5, lane = t & 31;
    const int warp_m = wid & 3;
    const int warp_n = wid >> 2;
    const int r0 = blockIdx.x * 128;

    float acc[2][8][4];
#pragma unroll
    for (int i = 0; i < 2; ++i)
#pragma unroll
        for (int j = 0; j < 8; ++j) {
            acc[i][j][0] = 0.f; acc[i][j][1] = 0.f;
            acc[i][j][2] = 0.f; acc[i][j][3] = 0.f;
        }

    const int srow = t >> 1;
    const int shalf = (t & 1) * 16;
    int rowA = r0 + srow;
    if (rowA >= NN) rowA = NN - 1;   // clamped rows discarded in epilogue

    const int lg = lane >> 3, lr = lane & 7;
    const int roff = (lg & 1) * 8 + lr;
    const int koff = (lg >> 1) * 8;
    const int n = ga.nchunks;

    // stage issue: pure cp.async copies from pre-split planes
    auto issue = [&](int c, int st) {
        const Chunk ch = ga.ch[g][c];
        const __nv_bfloat16* ah = &g_sh[ch.a_base + rowA * ch.lda + shalf];
        const __nv_bfloat16* al = &g_sl[ch.a_base + rowA * ch.lda + shalf];
        const __nv_bfloat16* bh = &g_sh[ch.b_base + srow * ch.ldb + shalf];
        const __nv_bfloat16* bl = &g_sl[ch.b_base + srow * ch.ldb + shalf];
        uint32_t d = smb + st * STAGEB + (srow * SROW + shalf) * 2;
        CP16(d,           ah); CP16(d + 16,           ah + 8);
        CP16(d + PB,      al); CP16(d + PB + 16,      al + 8);
        CP16(d + 2 * PB,  bh); CP16(d + 2 * PB + 16,  bh + 8);
        CP16(d + 3 * PB,  bl); CP16(d + 3 * PB + 16,  bl + 8);
    };

    auto compute = [&](int st) {
        uint32_t b0 = smb + st * STAGEB;
#pragma unroll
        for (int k0 = 0; k0 < 32; k0 += 16) {
            uint32_t aH[2][4], aL[2][4], bH[4][4], bL[4][4];
#pragma unroll
            for (int mi = 0; mi < 2; ++mi) {
                int m = warp_m * 32 + mi * 16 + roff;
                uint32_t off = b0 + (uint32_t)(m * SROW + k0 + koff) * 2;
                ldsm4(aH[mi], off);
                ldsm4(aL[mi], off + PB);
            }
#pragma unroll
            for (int ni = 0; ni < 4; ++ni) {
                int nrow = warp_n * 64 + ni * 16 + roff;
                uint32_t off = b0 + (uint32_t)(nrow * SROW + k0 + koff) * 2;
                ldsm4(bH[ni], off + 2 * PB);
                ldsm4(bL[ni], off + 3 * PB);
            }
#pragma unroll
            for (int mi = 0; mi < 2; ++mi)
#pragma unroll
                for (int ni = 0; ni < 4; ++ni)
#pragma unroll
                    for (int sub = 0; sub < 2; ++sub) {
                        uint32_t b0h[2] = {bH[ni][sub], bH[ni][2 + sub]};
                        uint32_t b0l[2] = {bL[ni][sub], bL[ni][2 + sub]};
                        float* cc = acc[mi][ni * 2 + sub];
                        mma16816(cc, aH[mi], b0h);
                        mma16816(cc, aH[mi], b0l);
                        mma16816(cc, aL[mi], b0h);
                    }
        }
    };

    issue(0, 0); CPCOMMIT();
    for (int c = 0; c < n; ++c) {
        if (c + 1 < n) { issue(c + 1, (c + 1) & 1); CPCOMMIT(); CPWAIT1(); }
        else           { CPWAIT0(); }
        __syncthreads();
        compute(c & 1);
        __syncthreads();
    }

    // ---- epilogue ----
    const float* bias = ga.bias[g];
    float* outF = (ga.outF[g] >= 0) ? gbuf(ga.outF[g]) : nullptr;
    const int oS = ga.outS[g];
    const int tg = lane >> 2, tid4 = lane & 3;
#pragma unroll
    for (int j = 0; j < 8; ++j) {
        int col = warp_n * 64 + j * 8 + tid4 * 2;
        float2 bb = bias ? *(const float2*)&bias[col] : make_float2(0.f, 0.f);
#pragma unroll
        for (int mi = 0; mi < 2; ++mi) {
            int row0 = r0 + warp_m * 32 + mi * 16 + tg;
            float* cc = acc[mi][j];
            float2 v0 = make_float2(cc[0] + bb.x, cc[1] + bb.y);
            float2 v1 = make_float2(cc[2] + bb.x, cc[3] + bb.y);
            if (ga.doRelu) {
                v0.x = fmaxf(v0.x, 0.f); v0.y = fmaxf(v0.y, 0.f);
                v1.x = fmaxf(v1.x, 0.f); v1.y = fmaxf(v1.y, 0.f);
            }
            if (row0 < NN) {
                if (outF) *(float2*)&outF[(size_t)row0 * 128 + col] = v0;
                if (oS >= 0) {
                    uint32_t hi, lo;
                    split2(v0.x, v0.y, hi, lo);
                    int off = oS + row0 * 128 + col;
                    *(uint32_t*)&g_sh[off] = hi;
                    *(uint32_t*)&g_sl[off] = lo;
                }
            }
            int row1 = row0 + 8;
            if (row1 < NN) {
                if (outF) *(float2*)&outF[(size_t)row1 * 128 + col] = v1;
                if (oS >= 0) {
                    uint32_t hi, lo;
                    split2(v1.x, v1.y, hi, lo);
                    int off = oS + row1 * 128 + col;
                    *(uint32_t*)&g_sh[off] = hi;
                    *(uint32_t*)&g_sl[off] = lo;
                }
            }
        }
    }
}

// ---------------- edge classifier ----------------
__global__ void edge_cls_kernel(const int* __restrict__ tei, int Et,
                                const float* __restrict__ Wc2,
                                const float* __restrict__ bc2,
                                float* __restrict__ out) {
    int w    = (blockIdx.x * blockDim.x + threadIdx.x) >> 5;
    int lane = threadIdx.x & 31;
    if (w >= Et) return;
    int st = g_stride;
    int ru = tei[st * w];
    int rm = tei[st * (Et + w)];
    float4 u  = __ldg(&((const float4*)g_Pu)[ru * 32 + lane]);
    float4 m  = __ldg(&((const float4*)g_Pm)[rm * 32 + lane]);
    float4 wv = __ldg(&((const float4*)Wc2)[lane]);
    float a = fmaxf(u.x + m.x, 0.f) * wv.x
            + fmaxf(u.y + m.y, 0.f) * wv.y
            + fmaxf(u.z + m.z, 0.f) * wv.z
            + fmaxf(u.w + m.w, 0.f) * wv.w;
#pragma unroll
    for (int o = 16; o; o >>= 1) a += __shfl_xor_sync(0xffffffffu, a, o);
    if (lane == 0) out[w] = a + bc2[0];
}

// ---------------- host launcher ----------------
extern "C" void kernel_launch(void* const* d_in, const int* in_sizes, int n_in,
                              void* d_out, int out_size) {
    const float* x_user  = (const float*)d_in[0];
    const float* x_merch = (const float*)d_in[1];
    const int*   e_um    = (const int*)d_in[2];
    const int*   e_mu    = (const int*)d_in[3];
    const int*   tei     = (const int*)d_in[4];
    const float* W1_um_l = (const float*)d_in[5];
    const float* b1_um_l = (const float*)d_in[6];
    const float* W1_um_r = (const float*)d_in[7];
    const float* W1_mu_l = (const float*)d_in[8];
    const float* b1_mu_l = (const float*)d_in[9];
    const float* W1_mu_r = (const float*)d_in[10];
    const float* W2_um_l = (const float*)d_in[11];
    const float* b2_um_l = (const float*)d_in[12];
    const float* W2_um_r = (const float*)d_in[13];
    const float* W2_mu_l = (const float*)d_in[14];
    const float* b2_mu_l = (const float*)d_in[15];
    const float* W2_mu_r = (const float*)d_in[16];
    const float* Wc1     = (const float*)d_in[17];
    const float* bc1     = (const float*)d_in[18];
    const float* Wc2     = (const float*)d_in[19];
    const float* bc2     = (const float*)d_in[20];

    const int E  = EMAX;
    const int Et = ETGT;
    float* out = (float*)d_out;

    cudaFuncSetAttribute(gemm_mma_kernel,
                         cudaFuncAttributeMaxDynamicSharedMemorySize, SMEM_DYN);

    // 1) setup: zero counters, dtype detect, split weights & x
    SetupArgs sa;
    const float* srcs[11] = {W1_um_l, W1_um_r, W1_mu_l, W1_mu_r,
                             W2_um_l, W2_um_r, W2_mu_l, W2_mu_r, Wc1,
                             x_user, x_merch};
    int doffs[11] = {S_W + W1UL, S_W + W1UR, S_W + W1ML, S_W + W1MR,
                     S_W + W2UL, S_W + W2UR, S_W + W2ML, S_W + W2MR, S_W + WC,
                     S_XU, S_XM};
    int pairs[11] = {4096, 4096, 4096, 4096, 8192, 8192, 8192, 8192, 16384,
                     1600000, 1600000};
    int run = 0;
    for (int i = 0; i < 11; ++i) {
        sa.src[i] = srcs[i]; sa.dstoff[i] = doffs[i];
        sa.start[i] = run; run += pairs[i];
    }
    sa.start[11] = run;
    sa.e_detect = e_um;
    setup_kernel<<<(run + 255) / 256, 256>>>(sa);

    // 2) CSR build
    const int EB = (E + 255) / 256;
    count_both_kernel<<<dim3(EB, 2), 256>>>(e_um, e_mu, E);
    scan_both_kernel<<<2, 1024>>>();
    scatter_both_kernel<<<dim3(EB, 2), 256>>>(e_um, e_mu, E);

    const int PB2 = (NN * 32 + 255) / 256;
    const int GB = (NN + 127) / 128;

    auto CHK = [](int ab, int bb, int lda, int ldb) {
        Chunk c; c.a_base = ab; c.b_base = bb; c.lda = lda; c.ldb = ldb; return c;
    };

    // 3) layer 1 (relu): h = relu([mean1 | x_self] @ W + b)
    pull_pair_kernel<64><<<dim3(PB2, 2), 256>>>(x_user, -1, x_merch, -1,
                                                S_M1M, S_M1U);
    GArgs g1;
    for (int q = 0; q < 2; ++q) {
        g1.ch[0][q]     = CHK(S_M1M + 32 * q, S_W + W1UL + 32 * q, 64, 64);
        g1.ch[0][2 + q] = CHK(S_XM  + 32 * q, S_W + W1UR + 32 * q, 64, 64);
        g1.ch[1][q]     = CHK(S_M1U + 32 * q, S_W + W1ML + 32 * q, 64, 64);
        g1.ch[1][2 + q] = CHK(S_XU  + 32 * q, S_W + W1MR + 32 * q, 64, 64);
    }
    g1.bias[0] = b1_um_l; g1.bias[1] = b1_mu_l;
    g1.outF[0] = 0; g1.outF[1] = 1;          // h fp32 (for pull2)
    g1.outS[0] = S_HM; g1.outS[1] = S_HU;    // h split (for gemm2)
    g1.nchunks = 4; g1.doRelu = 1;
    gemm_mma_kernel<<<dim3(GB, 2), 256, SMEM_DYN>>>(g1);

    // 4) layer 2 (no relu): z = [mean2 | h_self] @ W + b  (split only)
    pull_pair_kernel<128><<<dim3(PB2, 2), 256>>>(nullptr, 1, nullptr, 0,
                                                 S_M2M, S_M2U);
    GArgs g2;
    for (int q = 0; q < 4; ++q) {
        g2.ch[0][q]     = CHK(S_M2M + 32 * q, S_W + W2UL + 32 * q, 128, 128);
        g2.ch[0][4 + q] = CHK(S_HM  + 32 * q, S_W + W2UR + 32 * q, 128, 128);
        g2.ch[1][q]     = CHK(S_M2U + 32 * q, S_W + W2ML + 32 * q, 128, 128);
        g2.ch[1][4 + q] = CHK(S_HU  + 32 * q, S_W + W2MR + 32 * q, 128, 128);
    }
    g2.bias[0] = b2_um_l; g2.bias[1] = b2_mu_l;
    g2.outF[0] = -1; g2.outF[1] = -1;
    g2.outS[0] = S_ZM; g2.outS[1] = S_ZU;
    g2.nchunks = 8; g2.doRelu = 0;
    gemm_mma_kernel<<<dim3(GB, 2), 256, SMEM_DYN>>>(g2);

    // 5) classifier projections: Pu = z_u@Wc1a + bc1, Pm = z_m@Wc1b
    GArgs gc;
    for (int q = 0; q < 4; ++q) {
        gc.ch[0][q] = CHK(S_ZU + 32 * q, S_W + WC + 32 * q,       128, 256);
        gc.ch[1][q] = CHK(S_ZM + 32 * q, S_W + WC + 128 + 32 * q, 128, 256);
    }
    gc.bias[0] = bc1; gc.bias[1] = nullptr;
    gc.outF[0] = 2; gc.outF[1] = 3;
    gc.outS[0] = -1; gc.outS[1] = -1;
    gc.nchunks = 4; gc.doRelu = 0;
    gemm_mma_kernel<<<dim3(GB, 2), 256, SMEM_DYN>>>(gc);

    // 6) per-edge output
    edge_cls_kernel<<<(Et * 32 + 255) / 256, 256>>>(tei, Et, Wc2, bc2, out);
}